// round 5
// baseline (speedup 1.0000x reference)
#include <cuda_runtime.h>

// Problem constants
#define NB      8
#define NS      8192
#define DIM     1024
#define NE      16
#define NTOK    (NB * NS)        // 65536 tokens
#define C4      (DIM / 4)        // 256 float4 per token row
#define CHUNKS  (C4 / 32)        // 8 float4 chunks per lane

// Tiling: 4-warp group covers 8 tokens x 16 experts; each warp 8 tokens x 4 experts.
// 32 accumulators/warp -> ~80 regs -> 3 blocks/SM (24 warps, occ 37.5%).
#define T       8                // tokens per warp
#define EH      4                // experts per warp (quarter of NE)
#define WARPS   8                // 2 groups of 4 warps
#define THREADS (WARPS * 32)
#define TOK_PER_BLOCK 16         // 2 groups * 8 tokens
#define GRID    (NTOK / TOK_PER_BLOCK)            // 4096

#define SMEM_BYTES (NE * DIM * 4 + WARPS * 32 * 4)  // 64KB W + 1KB logits

__global__ __launch_bounds__(THREADS, 3) void gating_kernel(
    const float* __restrict__ x,
    const float* __restrict__ W,
    const float* __restrict__ bias,
    float* __restrict__ out)
{
    extern __shared__ float smem[];
    float4* sW   = (float4*)smem;                  // [NE][C4] float4 = 64KB
    float*  sLog = smem + NE * DIM;                // [WARPS][32]

    // Cooperative load of W into shared (stays for whole block)
    {
        const float4* Wg = (const float4*)W;
        #pragma unroll
        for (int i = threadIdx.x; i < NE * C4; i += THREADS) sW[i] = Wg[i];
    }
    __syncthreads();

    const int warp = threadIdx.x >> 5;
    const int lane = threadIdx.x & 31;
    const int grp  = warp >> 2;        // 0..1, which 8-token group
    const int sub  = warp & 3;         // 0..3, which 4-expert slice
    const int token0 = blockIdx.x * TOK_PER_BLOCK + grp * T;

    // 32 accumulators: v[t*EH + e]
    float v[T * EH];
    #pragma unroll
    for (int k = 0; k < T * EH; k++) v[k] = 0.0f;

    const float4* x4  = (const float4*)x + (size_t)token0 * C4;
    const float4* sWh = sW + sub * EH * C4;

    // Main loop: lane handles float4 columns {lane + 32*i}.
    // Per chunk per warp: 8 LDG.128 (x; 3 of 4 group-mates hit L1),
    //                     4 LDS.128 (W) -> each feeds 32 FFMA; 128 FFMA total.
    for (int i = 0; i < CHUNKS; i++) {
        const int c = lane + 32 * i;
        float4 xv[T];
        #pragma unroll
        for (int t = 0; t < T; t++) xv[t] = x4[(size_t)t * C4 + c];

        #pragma unroll
        for (int e = 0; e < EH; e++) {
            float4 wv = sWh[e * C4 + c];
            #pragma unroll
            for (int t = 0; t < T; t++) {
                float a = v[t * EH + e];
                a = fmaf(xv[t].x, wv.x, a);
                a = fmaf(xv[t].y, wv.y, a);
                a = fmaf(xv[t].z, wv.z, a);
                a = fmaf(xv[t].w, wv.w, a);
                v[t * EH + e] = a;
            }
        }
    }

    // Value-splitting butterfly: 32 values over 32 lanes, 5 stages (31 shfl).
    // At stage with mask m, hi lanes keep the upper half (offset +m);
    // total offset = sum(m * bit(lane,m)) = lane, so lane l ends with
    // fully-reduced v[0] = original index l (= t*EH + e).
    #pragma unroll
    for (int m = 16; m >= 1; m >>= 1) {
        const bool hi = (lane & m) != 0;
        #pragma unroll
        for (int j = 0; j < m; j++) {
            float send = hi ? v[j] : v[j + m];
            float keep = hi ? v[j + m] : v[j];
            v[j] = keep + __shfl_xor_sync(0xffffffffu, send, m);
        }
    }

    // Stage: slot l of warp w holds token l/4 (of group w/4), expert (w&3)*4 + l%4.
    sLog[warp * 32 + lane] = v[0];
    __syncthreads();

    // Epilogue: warp 0, lanes 0..15 each own one token (token = base + lane).
    if (warp == 0 && lane < TOK_PER_BLOCK) {
        const int g = lane >> 3;          // which group's logits
        const int t = lane & 7;           // token within group
        const int token = blockIdx.x * TOK_PER_BLOCK + lane;

        float lg[NE];
        float mx = -1e30f;
        #pragma unroll
        for (int e = 0; e < NE; e++) {
            lg[e] = sLog[(g * 4 + (e >> 2)) * 32 + t * 4 + (e & 3)] + __ldg(&bias[e]);
            mx = fmaxf(mx, lg[e]);
        }
        float s = 0.0f;
        #pragma unroll
        for (int e = 0; e < NE; e++) {
            lg[e] = __expf(lg[e] - mx);
            s += lg[e];
        }
        const float inv = 1.0f / s;

        // top-2 (strict > keeps first index on ties, matching jax top_k)
        int i1 = 0; float m1 = lg[0];
        #pragma unroll
        for (int e = 1; e < NE; e++) if (lg[e] > m1) { m1 = lg[e]; i1 = e; }
        int i2 = -1; float m2 = -1.0f;
        #pragma unroll
        for (int e = 0; e < NE; e++) if (e != i1 && lg[e] > m2) { m2 = lg[e]; i2 = e; }

        float* gated = out;                         // [NE, NB, NS]
        float* wout  = out + (size_t)NE * NTOK;     // [NE, NB, NS]
        #pragma unroll
        for (int e = 0; e < NE; e++) {
            const float w = lg[e] * inv;
            wout [(size_t)e * NTOK + token] = w;
            gated[(size_t)e * NTOK + token] = (e == i1 || e == i2) ? w : 0.0f;
        }
    }
}

extern "C" void kernel_launch(void* const* d_in, const int* in_sizes, int n_in,
                              void* d_out, int out_size)
{
    (void)in_sizes; (void)n_in; (void)out_size;
    const float* x = (const float*)d_in[0];
    const float* W = (const float*)d_in[1];
    const float* b = (const float*)d_in[2];
    float* out = (float*)d_out;

    cudaFuncSetAttribute(gating_kernel,
                         cudaFuncAttributeMaxDynamicSharedMemorySize, SMEM_BYTES);
    gating_kernel<<<GRID, THREADS, SMEM_BYTES>>>(x, W, b, out);
}

// round 8
// speedup vs baseline: 1.1889x; 1.1889x over previous
#include <cuda_runtime.h>
#include <cstdint>

// Problem constants
#define NB      8
#define NS      8192
#define DIM     1024
#define NE      16
#define NTOK    (NB * NS)        // 65536 tokens

// Tiling: warp-pair covers 8 tokens x 16 experts.
// Each warp: 8 tokens x 4 expert-PAIRS {e', e'+8} via packed f32x2 FFMA2.
#define T       8
#define JP      4                 // expert pairs per warp
#define WARPS   8                 // 4 warp-pairs
#define THREADS (WARPS * 32)
#define TOK_PER_BLOCK 32
#define GRID    (NTOK / TOK_PER_BLOCK)   // 2048

// smem: sW2 = 8 rows (e'=0..7) x 1024 k x f32x2 {W[e'],W[e'+8]} = 64KB
//       sLog = 32 tokens x 16 experts floats = 2KB
#define SMEM_BYTES (8 * DIM * 8 + TOK_PER_BLOCK * NE * 4)

typedef unsigned long long u64;

static __device__ __forceinline__ u64 fma2(u64 a, u64 b, u64 c) {
    u64 d;
    asm("fma.rn.f32x2 %0, %1, %2, %3;" : "=l"(d) : "l"(a), "l"(b), "l"(c));
    return d;
}
static __device__ __forceinline__ u64 add2(u64 a, u64 b) {
    u64 d;
    asm("add.rn.f32x2 %0, %1, %2;" : "=l"(d) : "l"(a), "l"(b));
    return d;
}
static __device__ __forceinline__ u64 bcast2(float x) {
    u64 d;
    asm("mov.b64 %0, {%1, %1};" : "=l"(d) : "r"(__float_as_uint(x)));
    return d;
}

__global__ __launch_bounds__(THREADS, 2) void gating_kernel(
    const float* __restrict__ x,
    const float* __restrict__ W,
    const float* __restrict__ bias,
    float* __restrict__ out)
{
    extern __shared__ float smem[];
    u64*   sW2  = (u64*)smem;                       // [8][1024] f32x2
    float* sLog = smem + 8 * DIM * 2;               // [32][16]

    // Build interleaved W pairs: sW2[e'][k] = {W[e'][k], W[e'+8][k]}
    for (int i = threadIdx.x; i < 8 * DIM; i += THREADS) {
        const int ep = i >> 10, k = i & (DIM - 1);
        float2 p;
        p.x = W[ep * DIM + k];
        p.y = W[(ep + 8) * DIM + k];
        ((float2*)sW2)[i] = p;
    }
    __syncthreads();

    const int warp = threadIdx.x >> 5;
    const int lane = threadIdx.x & 31;
    const int pairId = warp >> 1;     // 0..3 token group
    const int half   = warp & 1;      // which 4 expert-pairs
    const int token0 = blockIdx.x * TOK_PER_BLOCK + pairId * T;

    // 32 f32x2 accumulators: v[t*4+j] = {logit[e'], logit[e'+8]}, e'=half*4+j
    u64 v[T * JP];
    #pragma unroll
    for (int k = 0; k < T * JP; k++) v[k] = 0ull;

    const float* xbase = x + (size_t)token0 * DIM;
    const u64*   sWh   = sW2 + (half * JP) * DIM;

    // Super-chunk = 128 k (lanes cover k0 = sc*128 + 2*lane, two 64-k halves).
    // Per half: 8 LDG.64 (contiguous 256B/warp), 16 mov.b64 broadcasts,
    //           4 LDS.128 (16B lane stride, conflict-free), 64 FFMA2.
    for (int sc = 0; sc < 8; sc++) {
        const int kbase = sc * 128 + 2 * lane;
        #pragma unroll
        for (int h2 = 0; h2 < 2; h2++) {
            const int k0 = kbase + 64 * h2;
            float2 xa[T];
            #pragma unroll
            for (int t = 0; t < T; t++)
                xa[t] = *(const float2*)(xbase + t * DIM + k0);
            u64 px[T][2];
            #pragma unroll
            for (int t = 0; t < T; t++) {
                px[t][0] = bcast2(xa[t].x);
                px[t][1] = bcast2(xa[t].y);
            }
            #pragma unroll
            for (int j = 0; j < JP; j++) {
                ulonglong2 w2 = *(const ulonglong2*)(sWh + j * DIM + k0);
                #pragma unroll
                for (int t = 0; t < T; t++) {
                    u64 a = v[t * JP + j];
                    a = fma2(px[t][0], w2.x, a);
                    a = fma2(px[t][1], w2.y, a);
                    v[t * JP + j] = a;
                }
            }
        }
    }

    // Value-splitting butterfly on 32 f32x2 values: lane l ends with
    // fully-reduced v[0] = original index l (t = l>>2, j = l&3).
    #pragma unroll
    for (int m = 16; m >= 1; m >>= 1) {
        const bool hi = (lane & m) != 0;
        #pragma unroll
        for (int j = 0; j < m; j++) {
            u64 send = hi ? v[j] : v[j + m];
            u64 keep = hi ? v[j + m] : v[j];
            v[j] = add2(keep, __shfl_xor_sync(0xffffffffu, send, m));
        }
    }

    // Stage logits: token row = pairId*8 + (l>>2); experts e'=half*4+(l&3), +8.
    {
        uint32_t lo, hi;
        asm("mov.b64 {%0, %1}, %2;" : "=r"(lo), "=r"(hi) : "l"(v[0]));
        const int trow = pairId * T + (lane >> 2);
        const int ep   = half * JP + (lane & 3);
        sLog[trow * NE + ep]     = __uint_as_float(lo);
        sLog[trow * NE + ep + 8] = __uint_as_float(hi);
    }
    __syncthreads();

    // Epilogue: warp 0, lane = token row -> fully coalesced stores.
    if (warp == 0) {
        const int token = blockIdx.x * TOK_PER_BLOCK + lane;
        const float* my = sLog + lane * NE;

        float lg[NE];
        float mx = -1e30f;
        #pragma unroll
        for (int e = 0; e < NE; e++) {
            lg[e] = my[e] + __ldg(&bias[e]);
            mx = fmaxf(mx, lg[e]);
        }
        float s = 0.0f;
        #pragma unroll
        for (int e = 0; e < NE; e++) { lg[e] = __expf(lg[e] - mx); s += lg[e]; }
        const float inv = 1.0f / s;

        // top-2 (strict > keeps first index on ties, matching jax top_k)
        int i1 = 0; float m1 = lg[0];
        #pragma unroll
        for (int e = 1; e < NE; e++) if (lg[e] > m1) { m1 = lg[e]; i1 = e; }
        int i2 = -1; float m2 = -1.0f;
        #pragma unroll
        for (int e = 0; e < NE; e++) if (e != i1 && lg[e] > m2) { m2 = lg[e]; i2 = e; }

        float* gated = out;                         // [NE, NB, NS]
        float* wout  = out + (size_t)NE * NTOK;     // [NE, NB, NS]
        #pragma unroll
        for (int e = 0; e < NE; e++) {
            const float w = lg[e] * inv;
            wout [(size_t)e * NTOK + token] = w;
            gated[(size_t)e * NTOK + token] = (e == i1 || e == i2) ? w : 0.0f;
        }
    }
}

extern "C" void kernel_launch(void* const* d_in, const int* in_sizes, int n_in,
                              void* d_out, int out_size)
{
    (void)in_sizes; (void)n_in; (void)out_size;
    const float* x = (const float*)d_in[0];
    const float* W = (const float*)d_in[1];
    const float* b = (const float*)d_in[2];
    float* out = (float*)d_out;

    cudaFuncSetAttribute(gating_kernel,
                         cudaFuncAttributeMaxDynamicSharedMemorySize, SMEM_BYTES);
    gating_kernel<<<GRID, THREADS, SMEM_BYTES>>>(x, W, b, out);
}

// round 9
// speedup vs baseline: 1.2478x; 1.0496x over previous
#include <cuda_runtime.h>
#include <cstdint>

// Problem constants
#define NB      8
#define NS      8192
#define DIM     1024
#define NE      16
#define NTOK    (NB * NS)        // 65536 tokens

// Tiling: warp-pair covers 8 tokens x 16 experts (4 FFMA2 expert-pairs/warp).
#define T       8
#define JP      4
#define WARPS   8
#define THREADS (WARPS * 32)
#define TOK_PER_BLOCK 32
#define GRID    (NTOK / TOK_PER_BLOCK)   // 2048

// cp.async pipeline: 16 stages of 64 k, 4 buffers of 8KB.
#define KS      64
#define NSTAGE  (DIM / KS)       // 16
#define DEPTH   4

// smem (floats): sW2 8x1024 f32x2 = 64KB | sX 4x32x64 = 32KB | sLog 2KB
#define SW2_F   (8 * DIM * 2)
#define SX_F    (DEPTH * TOK_PER_BLOCK * KS)
#define SMEM_BYTES ((SW2_F + SX_F + TOK_PER_BLOCK * NE) * 4)

typedef unsigned long long u64;

static __device__ __forceinline__ u64 fma2(u64 a, u64 b, u64 c) {
    u64 d;
    asm("fma.rn.f32x2 %0, %1, %2, %3;" : "=l"(d) : "l"(a), "l"(b), "l"(c));
    return d;
}
static __device__ __forceinline__ u64 add2(u64 a, u64 b) {
    u64 d;
    asm("add.rn.f32x2 %0, %1, %2;" : "=l"(d) : "l"(a), "l"(b));
    return d;
}
static __device__ __forceinline__ u64 bcast2(float x) {
    u64 d;
    asm("mov.b64 %0, {%1, %1};" : "=l"(d) : "r"(__float_as_uint(x)));
    return d;
}
static __device__ __forceinline__ uint32_t s2u(const void* p) {
    uint32_t a;
    asm("{ .reg .u64 t; cvta.to.shared.u64 t, %1; cvt.u32.u64 %0, t; }"
        : "=r"(a) : "l"(p));
    return a;
}
static __device__ __forceinline__ void cpa16(uint32_t dst, const float* src) {
    asm volatile("cp.async.cg.shared.global [%0], [%1], 16;"
                 :: "r"(dst), "l"(src) : "memory");
}

__global__ __launch_bounds__(THREADS, 2) void gating_kernel(
    const float* __restrict__ x,
    const float* __restrict__ W,
    const float* __restrict__ bias,
    float* __restrict__ out)
{
    extern __shared__ float smem[];
    u64*   sW2  = (u64*)smem;                 // [8][1024] f32x2 expert pairs
    float* sX   = smem + SW2_F;               // [DEPTH][32][64]
    float* sLog = smem + SW2_F + SX_F;        // [32][16]

    const int tid  = threadIdx.x;
    const int warp = tid >> 5;
    const int lane = tid & 31;
    const int tok0 = blockIdx.x * TOK_PER_BLOCK;

    // Per-thread cp.async slots: 2 quads (16B) per stage.
    // quad q: row = q>>4 (16 quads per 64k row), kq = q&15.
    const uint32_t sXu = s2u(sX);
    const int rA = tid >> 4, kA = (tid & 15) * 4;
    const int rB = rA + 16;
    const uint32_t dA = (uint32_t)(rA * KS + kA) * 4u;
    const uint32_t dB = (uint32_t)(rB * KS + kA) * 4u;
    const float* gA = x + (size_t)(tok0 + rA) * DIM + kA;
    const float* gB = x + (size_t)(tok0 + rB) * DIM + kA;

    // Prologue: fire stages 0..DEPTH-2 (one commit group per stage).
    #pragma unroll
    for (int s = 0; s < DEPTH - 1; s++) {
        const uint32_t db = sXu + (uint32_t)(s * TOK_PER_BLOCK * KS * 4);
        cpa16(db + dA, gA + s * KS);
        cpa16(db + dB, gB + s * KS);
        asm volatile("cp.async.commit_group;" ::: "memory");
    }

    // Build interleaved W pairs: sW2[e'][k] = {W[e'][k], W[e'+8][k]}
    for (int i = tid; i < 8 * DIM; i += THREADS) {
        const int ep = i >> 10, k = i & (DIM - 1);
        float2 p;
        p.x = W[ep * DIM + k];
        p.y = W[(ep + 8) * DIM + k];
        ((float2*)sW2)[i] = p;
    }
    __syncthreads();

    const int pairId = warp >> 1;     // 0..3 token group
    const int half   = warp & 1;      // which 4 expert-pairs
    const u64* sWh   = sW2 + (half * JP) * DIM;
    const float* sXw = sX;            // indexed per stage below

    // 32 f32x2 accumulators: v[t*4+j] = {logit[e'], logit[e'+8]}
    u64 v[T * JP];
    #pragma unroll
    for (int k = 0; k < T * JP; k++) v[k] = 0ull;

    for (int sc = 0; sc < NSTAGE; sc++) {
        // Stage sc's data arrived when <=2 newer groups remain outstanding.
        asm volatile("cp.async.wait_group 2;" ::: "memory");
        __syncthreads();

        // Prefetch stage sc+DEPTH-1 (empty commit keeps group count uniform).
        const int pf = sc + DEPTH - 1;
        if (pf < NSTAGE) {
            const uint32_t db = sXu + (uint32_t)((pf & (DEPTH - 1)) * TOK_PER_BLOCK * KS * 4);
            cpa16(db + dA, gA + pf * KS);
            cpa16(db + dB, gB + pf * KS);
        }
        asm volatile("cp.async.commit_group;" ::: "memory");

        // Compute stage sc: lane owns k = {2*lane, 2*lane+1} of this 64-k slab.
        const float* xs = sXw + (sc & (DEPTH - 1)) * TOK_PER_BLOCK * KS
                        + pairId * T * KS + 2 * lane;
        const int kg = sc * KS + 2 * lane;

        u64 w2x[JP], w2y[JP];
        #pragma unroll
        for (int j = 0; j < JP; j++) {
            ulonglong2 w2 = *(const ulonglong2*)(sWh + j * DIM + kg);
            w2x[j] = w2.x; w2y[j] = w2.y;
        }
        #pragma unroll
        for (int t = 0; t < T; t++) {
            const float2 xa = *(const float2*)(xs + t * KS);
            const u64 p0 = bcast2(xa.x);
            const u64 p1 = bcast2(xa.y);
            #pragma unroll
            for (int j = 0; j < JP; j++) {
                u64 a = v[t * JP + j];
                a = fma2(p0, w2x[j], a);
                a = fma2(p1, w2y[j], a);
                v[t * JP + j] = a;
            }
        }
    }

    // Value-splitting butterfly on 32 f32x2: lane l ends with fully-reduced
    // v[0] = original index l (t = l>>2, j = l&3).
    #pragma unroll
    for (int m = 16; m >= 1; m >>= 1) {
        const bool hi = (lane & m) != 0;
        #pragma unroll
        for (int j = 0; j < m; j++) {
            u64 send = hi ? v[j] : v[j + m];
            u64 keep = hi ? v[j + m] : v[j];
            v[j] = add2(keep, __shfl_xor_sync(0xffffffffu, send, m));
        }
    }

    // Stage logits: token row = pairId*8 + (l>>2); experts half*4+(l&3), +8.
    {
        uint32_t lo, hi;
        asm("mov.b64 {%0, %1}, %2;" : "=r"(lo), "=r"(hi) : "l"(v[0]));
        const int trow = pairId * T + (lane >> 2);
        const int ep   = half * JP + (lane & 3);
        sLog[trow * NE + ep]     = __uint_as_float(lo);
        sLog[trow * NE + ep + 8] = __uint_as_float(hi);
    }
    __syncthreads();

    // Epilogue: warp 0, lane = token row -> fully coalesced stores.
    if (warp == 0) {
        const int token = tok0 + lane;
        const float* my = sLog + lane * NE;

        float lg[NE];
        float mx = -1e30f;
        #pragma unroll
        for (int e = 0; e < NE; e++) {
            lg[e] = my[e] + __ldg(&bias[e]);
            mx = fmaxf(mx, lg[e]);
        }
        float s = 0.0f;
        #pragma unroll
        for (int e = 0; e < NE; e++) { lg[e] = __expf(lg[e] - mx); s += lg[e]; }
        const float inv = 1.0f / s;

        // top-2 (strict > keeps first index on ties, matching jax top_k)
        int i1 = 0; float m1 = lg[0];
        #pragma unroll
        for (int e = 1; e < NE; e++) if (lg[e] > m1) { m1 = lg[e]; i1 = e; }
        int i2 = -1; float m2 = -1.0f;
        #pragma unroll
        for (int e = 0; e < NE; e++) if (e != i1 && lg[e] > m2) { m2 = lg[e]; i2 = e; }

        float* gated = out;                         // [NE, NB, NS]
        float* wout  = out + (size_t)NE * NTOK;     // [NE, NB, NS]
        #pragma unroll
        for (int e = 0; e < NE; e++) {
            const float w = lg[e] * inv;
            wout [(size_t)e * NTOK + token] = w;
            gated[(size_t)e * NTOK + token] = (e == i1 || e == i2) ? w : 0.0f;
        }
    }
}

extern "C" void kernel_launch(void* const* d_in, const int* in_sizes, int n_in,
                              void* d_out, int out_size)
{
    (void)in_sizes; (void)n_in; (void)out_size;
    const float* x = (const float*)d_in[0];
    const float* W = (const float*)d_in[1];
    const float* b = (const float*)d_in[2];
    float* out = (float*)d_out;

    cudaFuncSetAttribute(gating_kernel,
                         cudaFuncAttributeMaxDynamicSharedMemorySize, SMEM_BYTES);
    gating_kernel<<<GRID, THREADS, SMEM_BYTES>>>(x, W, b, out);
}

// round 11
// speedup vs baseline: 1.3171x; 1.0556x over previous
#include <cuda_runtime.h>
#include <cstdint>

// Problem constants
#define NB      8
#define NS      8192
#define DIM     1024
#define NE      16
#define NTOK    (NB * NS)          // 65536 tokens

#define M_TILE   128               // tokens per block (32 per warp)
#define THREADS  128
#define GRID     (NTOK / M_TILE)   // 512 blocks, single wave

// Ambiguity margin for top-2 selection (logit scale). TF32 3-term error ~1e-5,
// so any gap below this is re-arbitrated in exact fp32.
#define GUARD_EPS 5e-3f

static __device__ __forceinline__ void split_tf32(float v, uint32_t& hi, uint32_t& lo) {
    uint32_t h;
    asm("cvt.rna.tf32.f32 %0, %1;" : "=r"(h) : "f"(v));
    hi = h;
    lo = __float_as_uint(v - __uint_as_float(h));
}

static __device__ __forceinline__ void mma_tf32(float d[4],
                                                uint32_t a0, uint32_t a1,
                                                uint32_t a2, uint32_t a3,
                                                uint32_t b0, uint32_t b1) {
    asm volatile(
        "mma.sync.aligned.m16n8k8.row.col.f32.tf32.tf32.f32 "
        "{%0,%1,%2,%3}, {%4,%5,%6,%7}, {%8,%9}, {%0,%1,%2,%3};"
        : "+f"(d[0]), "+f"(d[1]), "+f"(d[2]), "+f"(d[3])
        : "r"(a0), "r"(a1), "r"(a2), "r"(a3), "r"(b0), "r"(b1));
}

__global__ __launch_bounds__(THREADS, 4) void gating_mma_kernel(
    const float* __restrict__ x,
    const float* __restrict__ W,
    const float* __restrict__ bias,
    float* __restrict__ out)
{
    __shared__ float sLog[THREADS / 32][32][NE];   // 8KB, epilogue staging only

    const int tid  = threadIdx.x;
    const int wid  = tid >> 5;
    const int lane = tid & 31;
    const int g    = lane >> 2;        // fragment group 0..7
    const int tg   = lane & 3;         // thread-in-group 0..3
    const int tokw = blockIdx.x * M_TILE + wid * 32;   // warp's 32-token base

    // K-PERMUTED fragments: for k8 group p, thread's K pair = {4tg+2p, 4tg+2p+1}.
    // Same per-thread permutation on A and B -> sum over K unchanged (exact).
    const float* xa = x + (size_t)(tokw + g) * DIM + 4 * tg;  // A rows g(+8,+16,+24)
    const float* wb = W + (size_t)g * DIM + 4 * tg;           // B experts g, g+8

    float acc[2][2][4];                // [m-tile][n-tile][frag]
    #pragma unroll
    for (int i = 0; i < 2; i++)
        #pragma unroll
        for (int j = 0; j < 2; j++)
            #pragma unroll
            for (int c = 0; c < 4; c++) acc[i][j][c] = 0.0f;

    #pragma unroll 2
    for (int k = 0; k < DIM; k += 16) {
        // 6 independent LDG.128 per thread (4 A rows, 2 B rows)
        float4 a[4], b[2];
        a[0] = *(const float4*)(xa + k);
        a[1] = *(const float4*)(xa + 8  * DIM + k);
        a[2] = *(const float4*)(xa + 16 * DIM + k);
        a[3] = *(const float4*)(xa + 24 * DIM + k);
        b[0] = *(const float4*)(wb + k);
        b[1] = *(const float4*)(wb + 8 * DIM + k);

        uint32_t ah[4][4], al[4][4], bh[2][4], bl[2][4];
        #pragma unroll
        for (int r = 0; r < 4; r++) {
            split_tf32(a[r].x, ah[r][0], al[r][0]);
            split_tf32(a[r].y, ah[r][1], al[r][1]);
            split_tf32(a[r].z, ah[r][2], al[r][2]);
            split_tf32(a[r].w, ah[r][3], al[r][3]);
        }
        #pragma unroll
        for (int r = 0; r < 2; r++) {
            split_tf32(b[r].x, bh[r][0], bl[r][0]);
            split_tf32(b[r].y, bh[r][1], bl[r][1]);
            split_tf32(b[r].z, bh[r][2], bl[r][2]);
            split_tf32(b[r].w, bh[r][3], bl[r][3]);
        }

        #pragma unroll
        for (int p = 0; p < 2; p++) {          // two k8 groups per k16
            const int c0 = 2 * p, c1 = 2 * p + 1;
            #pragma unroll
            for (int mt = 0; mt < 2; mt++) {
                const int r0 = mt * 2, r8 = mt * 2 + 1;
                #pragma unroll
                for (int nt = 0; nt < 2; nt++) {
                    float* d = acc[mt][nt];
                    // 3xTF32: hh + lh + hl (logit err ~1e-5; selection guarded)
                    mma_tf32(d, ah[r0][c0], ah[r8][c0], ah[r0][c1], ah[r8][c1],
                                bh[nt][c0], bh[nt][c1]);
                    mma_tf32(d, al[r0][c0], al[r8][c0], al[r0][c1], al[r8][c1],
                                bh[nt][c0], bh[nt][c1]);
                    mma_tf32(d, ah[r0][c0], ah[r8][c0], ah[r0][c1], ah[r8][c1],
                                bl[nt][c0], bl[nt][c1]);
                }
            }
        }
    }

    // Scatter accumulators: D row g/g+8 = token, col 2tg/2tg+1 = expert.
    #pragma unroll
    for (int mt = 0; mt < 2; mt++)
        #pragma unroll
        for (int nt = 0; nt < 2; nt++) {
            sLog[wid][mt * 16 + g    ][nt * 8 + 2 * tg    ] = acc[mt][nt][0];
            sLog[wid][mt * 16 + g    ][nt * 8 + 2 * tg + 1] = acc[mt][nt][1];
            sLog[wid][mt * 16 + g + 8][nt * 8 + 2 * tg    ] = acc[mt][nt][2];
            sLog[wid][mt * 16 + g + 8][nt * 8 + 2 * tg + 1] = acc[mt][nt][3];
        }
    __syncthreads();

    // Epilogue: thread t owns token tok0 + t -> fully coalesced stores.
    const int token = blockIdx.x * M_TILE + tid;
    const float* my = sLog[tid >> 5][tid & 31];

    float lg[NE];
    float mx = -1e30f;
    #pragma unroll
    for (int e = 0; e < NE; e++) {
        lg[e] = my[e] + __ldg(&bias[e]);
        mx = fmaxf(mx, lg[e]);
    }
    float s = 0.0f;
    #pragma unroll
    for (int e = 0; e < NE; e++) { lg[e] = __expf(lg[e] - mx); s += lg[e]; }
    const float inv = 1.0f / s;

    // top-3 on logits (monotone with weights); strict > keeps first on ties.
    float raw[NE];
    #pragma unroll
    for (int e = 0; e < NE; e++) raw[e] = my[e] + __ldg(&bias[e]);

    int i1 = 0; float m1 = raw[0];
    #pragma unroll
    for (int e = 1; e < NE; e++) if (raw[e] > m1) { m1 = raw[e]; i1 = e; }
    int i2 = -1; float m2 = -1e30f;
    #pragma unroll
    for (int e = 0; e < NE; e++) if (e != i1 && raw[e] > m2) { m2 = raw[e]; i2 = e; }
    int i3 = -1; float m3 = -1e30f;
    #pragma unroll
    for (int e = 0; e < NE; e++)
        if (e != i1 && e != i2 && raw[e] > m3) { m3 = raw[e]; i3 = e; }

    // Guard: if 2nd vs 3rd is within TF32 noise, arbitrate in exact fp32.
    int sel2 = i2;
    if (m2 - m3 < GUARD_EPS) {
        const float4* xr = (const float4*)(x + (size_t)token * DIM);
        const float4* w2 = (const float4*)(W + (size_t)i2 * DIM);
        const float4* w3 = (const float4*)(W + (size_t)i3 * DIM);
        float s2 = 0.0f, s3 = 0.0f;
        for (int q = 0; q < DIM / 4; q++) {
            const float4 xv = xr[q], a2 = w2[q], a3 = w3[q];
            s2 = fmaf(xv.x, a2.x, s2); s2 = fmaf(xv.y, a2.y, s2);
            s2 = fmaf(xv.z, a2.z, s2); s2 = fmaf(xv.w, a2.w, s2);
            s3 = fmaf(xv.x, a3.x, s3); s3 = fmaf(xv.y, a3.y, s3);
            s3 = fmaf(xv.z, a3.z, s3); s3 = fmaf(xv.w, a3.w, s3);
        }
        s2 += __ldg(&bias[i2]); s3 += __ldg(&bias[i3]);
        // Exact ranking; tie (==) keeps lower index like jax top_k.
        if (s3 > s2 || (s3 == s2 && i3 < i2)) sel2 = i3;
    }

    float* gated = out;                         // [NE, NB, NS]
    float* wout  = out + (size_t)NE * NTOK;     // [NE, NB, NS]
    #pragma unroll
    for (int e = 0; e < NE; e++) {
        const float w = lg[e] * inv;
        wout [(size_t)e * NTOK + token] = w;
        gated[(size_t)e * NTOK + token] = (e == i1 || e == sel2) ? w : 0.0f;
    }
}

extern "C" void kernel_launch(void* const* d_in, const int* in_sizes, int n_in,
                              void* d_out, int out_size)
{
    (void)in_sizes; (void)n_in; (void)out_size;
    const float* x = (const float*)d_in[0];
    const float* W = (const float*)d_in[1];
    const float* b = (const float*)d_in[2];
    float* out = (float*)d_out;

    gating_mma_kernel<<<GRID, THREADS>>>(x, W, b, out);
}